// round 4
// baseline (speedup 1.0000x reference)
#include <cuda_runtime.h>
#include <cstdint>

// ---------------- problem constants ----------------
#define NBLK 148
#define NTHR 256
#define BB   256
#define NC   3072            // compact gate width (i, gg, o) -- f gate is dead
#define TT   256
#define VV   130
#define BH   (256*1024)
#define GS   (256*3072)

// ---------------- persistent device scratch ----------------
__device__ float d_cT   [16*256*512];
__device__ float d_cPrev[16*256*512];
__device__ float d_hid  [16*256*1024];
__device__ float d_A1   [3*16*256*3072];
__device__ float d_CU   [16*256*3072];
__device__ float d_C2   [3*16*256*3072];
__device__ float d_E    [3*130*3072];
__device__ float d_nb1  [3*3072];
__device__ float d_h1   [3*256*1024];
__device__ float d_h2   [3*256*1024];
__device__ float d_ctxs [3*256*1024];
__device__ float d_uold [3*256*1024];
__device__ float d_unew [2*256*1024];
__device__ float d_s    [3*256*3072];
__device__ float d_sn   [2*256*3072];
__device__ float d_g    [3*256*3072];

// ---------------- grid barrier (replay-safe, sense via generation) ----------
__device__ unsigned int g_arrive;
__device__ unsigned int g_gen;

__device__ __forceinline__ void gsync()
{
    __threadfence();
    __syncthreads();
    if (threadIdx.x == 0) {
        volatile unsigned int* vg = &g_gen;
        unsigned int g = *vg;
        if (atomicAdd(&g_arrive, 1u) == (unsigned)(gridDim.x - 1)) {
            g_arrive = 0;
            __threadfence();
            *vg = g + 1u;
        } else {
            while (*vg == g) __nanosleep(32);
        }
        __threadfence();
    }
    __syncthreads();
}

// ---------------- f32x2 helpers ----------------
__device__ __forceinline__ void fma2(unsigned long long &c, unsigned long long a,
                                     unsigned long long b) {
    asm("fma.rn.f32x2 %0, %1, %2, %0;" : "+l"(c) : "l"(a), "l"(b));
}
__device__ __forceinline__ unsigned long long dup2(float a) {
    unsigned long long r;
    asm("mov.b64 %0, {%1, %1};" : "=l"(r) : "f"(a));
    return r;
}
__device__ __forceinline__ void unpack2(unsigned long long v, float &lo, float &hi) {
    asm("mov.b64 {%0, %1}, %2;" : "=f"(lo), "=f"(hi) : "l"(v));
}

// ---------------- generic fused GEMM stage ----------------
struct GP {
    const float* A;  long long lda,  Az;
    const float* B;  long long ldb,  Bz;
    const float* A2; long long lda2, A2z;
    const float* B2; long long ldb2, B2z;
    int K, K2, M, N, zc, compact, epi;   // epi: 0 none, 1 tanh
    float* C; long long ldc, Cz;
    const float* add0; long long add0z;
    const float* add1;
    const float* add2;
    const float* bias; long long biasz; int biasCompact;
    const float* Eg;  long long Egz;
    const int*  tok;  long long tokz;  int tokstride;
};

__device__ __forceinline__ void run_mm(const float* A, long long lda, int M, int m0,
                                       const float* Bb, long long ldb, int N, int n0, int K,
                                       float (&As)[16][64], float (&Bs)[16][64],
                                       unsigned long long (&acc)[4][2],
                                       int tid, int tx, int ty)
{
    int r  = tid >> 2;
    int kq = (tid & 3) << 2;
    bool am = (m0 + r < M);
    bool bn = (n0 + r < N);
    const float* Arow = A  + (long long)(m0 + r) * lda + kq;
    const float* Brow = Bb + (long long)r * ldb + kq;
    for (int k0 = 0; k0 < K; k0 += 16) {
        float4 av = am ? *(const float4*)(Arow + k0) : make_float4(0.f,0.f,0.f,0.f);
        float4 bv = bn ? *(const float4*)(Brow + k0) : make_float4(0.f,0.f,0.f,0.f);
        As[kq+0][r]=av.x; As[kq+1][r]=av.y; As[kq+2][r]=av.z; As[kq+3][r]=av.w;
        Bs[kq+0][r]=bv.x; Bs[kq+1][r]=bv.y; Bs[kq+2][r]=bv.z; Bs[kq+3][r]=bv.w;
        __syncthreads();
#pragma unroll
        for (int kk = 0; kk < 16; kk++) {
            unsigned long long b0 = *(const unsigned long long*)&Bs[kk][tx*4];
            unsigned long long b1 = *(const unsigned long long*)&Bs[kk][tx*4+2];
#pragma unroll
            for (int mi = 0; mi < 4; mi++) {
                unsigned long long a2 = dup2(As[kk][ty*4+mi]);
                fma2(acc[mi][0], a2, b0);
                fma2(acc[mi][1], a2, b1);
            }
        }
        __syncthreads();
    }
}

__device__ void gemm_stage(const GP& g, float (&As)[16][64], float (&Bs)[16][64])
{
    int mT = (g.M + 63) >> 6;
    int nT = (g.N + 63) >> 6;
    int total = g.zc * mT * nT;
    int tid = threadIdx.x;
    int tx = tid & 15, ty = tid >> 4;

    for (int tile = blockIdx.x; tile < total; tile += gridDim.x) {
        int z  = tile / (mT * nT);
        int r  = tile - z * (mT * nT);
        int mi0 = r / nT;
        int m0 = mi0 << 6;
        int n0 = (r - mi0 * nT) << 6;
        int noff = (g.compact && n0 >= 1024) ? 1024 : 0;

        unsigned long long acc[4][2];
#pragma unroll
        for (int i = 0; i < 4; i++) { acc[i][0] = 0ull; acc[i][1] = 0ull; }

        {
            const float* A  = g.A + (long long)z * g.Az;
            const float* Bb = g.B + (long long)z * g.Bz + (long long)(n0 + noff) * g.ldb;
            run_mm(A, g.lda, g.M, m0, Bb, g.ldb, g.N, n0, g.K, As, Bs, acc, tid, tx, ty);
        }
        if (g.A2) {
            const float* A  = g.A2 + (long long)z * g.A2z;
            const float* Bb = g.B2 + (long long)z * g.B2z + (long long)(n0 + noff) * g.ldb2;
            run_mm(A, g.lda2, g.M, m0, Bb, g.ldb2, g.N, n0, g.K2, As, Bs, acc, tid, tx, ty);
        }

        float* C = g.C + (long long)z * g.Cz;
#pragma unroll
        for (int mi = 0; mi < 4; mi++) {
            int m = m0 + ty * 4 + mi;
            if (m >= g.M) continue;
            float cv[4];
            unpack2(acc[mi][0], cv[0], cv[1]);
            unpack2(acc[mi][1], cv[2], cv[3]);
            long long token = 0;
            if (g.Eg) token = g.tok[(long long)z * g.tokz + (long long)m * g.tokstride];
#pragma unroll
            for (int nj = 0; nj < 4; nj++) {
                int n = n0 + tx * 4 + nj;
                if (n >= g.N) continue;
                float v = cv[nj];
                if (g.add0) v += g.add0[(long long)z * g.add0z + (long long)m * g.N + n];
                if (g.add1) v += g.add1[(long long)m * g.N + n];
                if (g.add2) v += g.add2[(long long)m * g.N + n];
                if (g.bias) v += g.bias[(long long)z * g.biasz + (g.biasCompact ? (n + noff) : n)];
                if (g.Eg)   v += g.Eg[(long long)z * g.Egz + token * g.N + n];
                if (g.epi == 1) v = tanhf(v);
                C[(long long)m * g.ldc + n] = v;
            }
        }
    }
}

// gate: h = sigmoid(o) * tanh(sigmoid(i) * tanh(gg)); compact layout [i|gg|o]
__device__ void gate_stage(const float* gsrc, long long gz, int zc,
                           float* dst0, long long d0z, float* dst1, long long d1z)
{
    int total = zc << 18;
    for (int idx = blockIdx.x * NTHR + threadIdx.x; idx < total; idx += gridDim.x * NTHR) {
        int z   = idx >> 18;
        int rem = idx & ((1 << 18) - 1);
        int m = rem >> 10, j = rem & 1023;
        const float* gp = gsrc + (long long)z * gz + (long long)m * NC;
        float gi = gp[j], gg = gp[1024 + j], go = gp[2048 + j];
        float si = 1.f / (1.f + expf(-gi));
        float so = 1.f / (1.f + expf(-go));
        float v  = so * tanhf(si * tanhf(gg));
        long long o = (long long)z * d0z + (long long)m * 1024 + j;
        dst0[o] = v;
        if (dst1) dst1[(long long)z * d1z + (long long)m * 1024 + j] = v;
    }
}

__device__ void reset_stage(const float* hid)
{
    for (int idx = blockIdx.x * NTHR + threadIdx.x; idx < (1 << 18);
         idx += gridDim.x * NTHR) {
        float v = hid[idx];
        d_h1[idx] = v; d_h1[BH + idx] = v; d_h1[2 * BH + idx] = v;
        d_h2[idx] = v; d_h2[BH + idx] = v; d_h2[2 * BH + idx] = v;
        d_ctxs[2 * BH + idx] = v;
    }
}

__device__ void prep_stage(const float* c)
{
    for (int idx = blockIdx.x * NTHR + threadIdx.x; idx < (16 * 256 * 512);
         idx += gridDim.x * NTHR) {
        int ptr = idx >> 17;
        int rem = idx & 131071;
        int b = rem >> 9, k = rem & 511;
        d_cT[idx] = c[((b << 4) + ptr) * 512 + k];
        int pm = ptr > 0 ? ptr - 1 : 0;
        d_cPrev[idx] = c[((b << 4) + pm) * 512 + k];
    }
}

__device__ void nb1_stage(const float* emb, const float* W1ih, const float* b1)
{
    for (int idx = blockIdx.x * NTHR + threadIdx.x; idx < 3 * 3072;
         idx += gridDim.x * NTHR) {
        int i = idx / 3072, n = idx - (idx / 3072) * 3072;
        int nfull = n + (n >= 1024 ? 1024 : 0);
        const float* e = emb + (long long)i * 130 * 512;            // v = 0 row
        const float* w = W1ih + ((long long)i * 4096 + nfull) * 1024;
        float s = b1[i * 4096 + nfull];
        for (int k = 0; k < 512; k++) s += e[k] * w[k];
        d_nb1[idx] = s;
    }
}

// ---------------- the single persistent kernel ----------------
__global__ void __launch_bounds__(NTHR, 1)
mega_kernel(const float* c, const float* W1ih, const float* W1hh, const float* b1,
            const float* cWih, const float* cWhh, const float* cb,
            const float* W2ih, const float* W2hh, const float* b2,
            const float* outW, const float* outb,
            const float* hidW, const float* hidb,
            const float* emb, const int* tgt, float* out)
{
    __shared__ __align__(16) float As[16][64];
    __shared__ __align__(16) float Bs[16][64];

    // ---- phase 0: transpose + notes0 hoist ----
    prep_stage(c);
    nb1_stage(emb, W1ih, b1);
    gsync();

    // ---- phase 1: all per-bar hoisted GEMMs ----
    { // hidden[ptr] = tanh(cPrev @ hidW^T + hidb)
        GP g = {};
        g.A = d_cPrev; g.lda = 512; g.B = hidW; g.ldb = 512;
        g.K = 512; g.M = 4096; g.N = 1024; g.zc = 1; g.epi = 1;
        g.C = d_hid; g.ldc = 1024;
        g.bias = hidb;
        gemm_stage(g, As, Bs);
    }
    { // A1[i][ptr] = nb1[i] + cT @ W1ih[i][:,512:]^T
        GP g = {};
        g.A = d_cT; g.lda = 512;
        g.B = W1ih + 512; g.ldb = 1024; g.Bz = (long long)4096 * 1024;
        g.K = 512; g.M = 4096; g.N = NC; g.zc = 3; g.compact = 1;
        g.C = d_A1; g.ldc = NC; g.Cz = (long long)16 * GS;
        g.bias = d_nb1; g.biasz = NC;
        gemm_stage(g, As, Bs);
    }
    { // CU[ptr] = cT @ W1ih[1][:,512:]^T + b1[1]
        GP g = {};
        g.A = d_cT; g.lda = 512;
        g.B = W1ih + (long long)4096 * 1024 + 512; g.ldb = 1024;
        g.K = 512; g.M = 4096; g.N = NC; g.zc = 1; g.compact = 1;
        g.C = d_CU; g.ldc = NC;
        g.bias = b1 + 4096; g.biasCompact = 1;
        gemm_stage(g, As, Bs);
    }
    { // C2[i][ptr] = cT @ W2ih[i][:,1024:]^T + b2[i]
        GP g = {};
        g.A = d_cT; g.lda = 512;
        g.B = W2ih + 1024; g.ldb = 1536; g.Bz = (long long)4096 * 1536;
        g.K = 512; g.M = 4096; g.N = NC; g.zc = 3; g.compact = 1;
        g.C = d_C2; g.ldc = NC; g.Cz = (long long)16 * GS;
        g.bias = b2; g.biasz = 4096; g.biasCompact = 1;
        gemm_stage(g, As, Bs);
    }
    { // E = emb @ W1ih[1][:, :512]^T
        GP g = {};
        g.A = emb; g.lda = 512;
        g.B = W1ih + (long long)4096 * 1024; g.ldb = 1024;
        g.K = 512; g.M = 390; g.N = NC; g.zc = 1; g.compact = 1;
        g.C = d_E; g.ldc = NC;
        gemm_stage(g, As, Bs);
    }
    gsync();

    // ---- time loop ----
    for (int t = 0; t < TT; t++) {
        int ptr = t >> 4;
        if ((t & 15) == 0) {
            reset_stage(d_hid + (long long)ptr * BH);
            gsync();
        }

        { // g = A1[.,ptr] + h1 @ W1hh^T
            GP g = {};
            g.A = d_h1; g.lda = 1024; g.Az = BH;
            g.B = W1hh; g.ldb = 1024; g.Bz = (long long)4096 * 1024;
            g.K = 1024; g.M = BB; g.N = NC; g.zc = 3; g.compact = 1;
            g.C = d_g; g.ldc = NC; g.Cz = GS;
            g.add0 = d_A1 + (long long)ptr * GS; g.add0z = (long long)16 * GS;
            gemm_stage(g, As, Bs);
        }
        gsync();
        gate_stage(d_g, GS, 3, d_h1, BH, d_uold, BH);
        gsync();

        { // s[i] = uold[i] @ ctxWih slice^T
            GP g = {};
            g.A = d_uold; g.lda = 1024; g.Az = BH;
            g.B = cWih; g.ldb = NC; g.Bz = 1024;
            g.K = 1024; g.M = BB; g.N = NC; g.zc = 3; g.compact = 1;
            g.C = d_s; g.ldc = NC; g.Cz = GS;
            gemm_stage(g, As, Bs);
        }
        { // gu[i] = E[i][tok] + CU[ptr] + uold[i] @ W1hh[1]^T   (i = 0,1)
            GP g = {};
            g.A = d_uold; g.lda = 1024; g.Az = BH;
            g.B = W1hh + (long long)4096 * 1024; g.ldb = 1024;
            g.K = 1024; g.M = BB; g.N = NC; g.zc = 2; g.compact = 1;
            g.C = d_g; g.ldc = NC; g.Cz = GS;
            g.add0 = d_CU + (long long)ptr * GS; g.add0z = 0;
            g.Eg = d_E; g.Egz = (long long)130 * NC;
            g.tok = tgt + t; g.tokz = 65536; g.tokstride = 256;
            gemm_stage(g, As, Bs);
        }
        gsync();
        gate_stage(d_g, GS, 2, d_unew, BH, (float*)0, 0);
        gsync();

        { // sn[i] = unew[i] @ ctxWih slice^T  (i = 0,1)
            GP g = {};
            g.A = d_unew; g.lda = 1024; g.Az = BH;
            g.B = cWih; g.ldb = NC; g.Bz = 1024;
            g.K = 1024; g.M = BB; g.N = NC; g.zc = 2; g.compact = 1;
            g.C = d_sn; g.ldc = NC; g.Cz = GS;
            gemm_stage(g, As, Bs);
        }
        { // ctx update 0 (can share phase with sn)
            GP g = {};
            g.A = d_ctxs + 2 * (long long)BH; g.lda = 1024;
            g.B = cWhh; g.ldb = 1024;
            g.K = 1024; g.M = BB; g.N = NC; g.zc = 1; g.compact = 1;
            g.C = d_g; g.ldc = NC;
            g.add0 = d_s; g.add0z = 0;
            g.add1 = d_s + GS; g.add2 = d_s + 2 * (long long)GS;
            g.bias = cb; g.biasCompact = 1;
            gemm_stage(g, As, Bs);
        }
        gsync();
        gate_stage(d_g, 0, 1, d_ctxs, 0, (float*)0, 0);
        gsync();

        { // ctx update 1
            GP g = {};
            g.A = d_ctxs; g.lda = 1024;
            g.B = cWhh; g.ldb = 1024;
            g.K = 1024; g.M = BB; g.N = NC; g.zc = 1; g.compact = 1;
            g.C = d_g; g.ldc = NC;
            g.add0 = d_sn; g.add0z = 0;
            g.add1 = d_s + GS; g.add2 = d_s + 2 * (long long)GS;
            g.bias = cb; g.biasCompact = 1;
            gemm_stage(g, As, Bs);
        }
        gsync();
        gate_stage(d_g, 0, 1, d_ctxs + BH, 0, (float*)0, 0);
        gsync();

        { // ctx update 2
            GP g = {};
            g.A = d_ctxs + (long long)BH; g.lda = 1024;
            g.B = cWhh; g.ldb = 1024;
            g.K = 1024; g.M = BB; g.N = NC; g.zc = 1; g.compact = 1;
            g.C = d_g; g.ldc = NC;
            g.add0 = d_sn; g.add0z = 0;
            g.add1 = d_sn + GS; g.add2 = d_s + 2 * (long long)GS;
            g.bias = cb; g.biasCompact = 1;
            gemm_stage(g, As, Bs);
        }
        gsync();
        gate_stage(d_g, 0, 1, d_ctxs + 2 * (long long)BH, 0, (float*)0, 0);
        gsync();

        { // g2[i] = ctxs[i] @ W2ih[i][:, :1024]^T + h2[i] @ W2hh[i]^T + C2[i][ptr]
            GP g = {};
            g.A = d_ctxs; g.lda = 1024; g.Az = BH;
            g.B = W2ih; g.ldb = 1536; g.Bz = (long long)4096 * 1536;
            g.K = 1024;
            g.A2 = d_h2; g.lda2 = 1024; g.A2z = BH;
            g.B2 = W2hh; g.ldb2 = 1024; g.B2z = (long long)4096 * 1024;
            g.K2 = 1024;
            g.M = BB; g.N = NC; g.zc = 3; g.compact = 1;
            g.C = d_g; g.ldc = NC; g.Cz = GS;
            g.add0 = d_C2 + (long long)ptr * GS; g.add0z = (long long)16 * GS;
            gemm_stage(g, As, Bs);
        }
        gsync();
        gate_stage(d_g, GS, 3, d_h2, BH, (float*)0, 0);
        gsync();

        { // out[i][:,t,:] = (uold[i] + h2[i]) @ outW[i]^T + outb[i]
            GP g = {};
            g.A = d_uold; g.lda = 1024; g.Az = BH;
            g.B = outW; g.ldb = 1024; g.Bz = (long long)130 * 1024;
            g.K = 1024;
            g.A2 = d_h2; g.lda2 = 1024; g.A2z = BH;
            g.B2 = outW; g.ldb2 = 1024; g.B2z = (long long)130 * 1024;
            g.K2 = 1024;
            g.M = BB; g.N = VV; g.zc = 3;
            g.C = out + (long long)t * VV; g.ldc = (long long)TT * VV;
            g.Cz = (long long)BB * TT * VV;
            g.bias = outb; g.biasz = VV;
            gemm_stage(g, As, Bs);
        }
        gsync();   // protects uold/h2 (read by OUT) from next step's writers
    }
}

// ---------------- host ----------------
extern "C" void kernel_launch(void* const* d_in, const int* in_sizes, int n_in,
                              void* d_out, int out_size)
{
    (void)in_sizes; (void)n_in; (void)out_size;
    mega_kernel<<<NBLK, NTHR>>>(
        (const float*)d_in[0],  (const float*)d_in[1],  (const float*)d_in[2],
        (const float*)d_in[3],  (const float*)d_in[4],  (const float*)d_in[5],
        (const float*)d_in[6],  (const float*)d_in[7],  (const float*)d_in[8],
        (const float*)d_in[9],  (const float*)d_in[10], (const float*)d_in[11],
        (const float*)d_in[12], (const float*)d_in[13], (const float*)d_in[14],
        (const int*)d_in[15],   (float*)d_out);
}

// round 5
// speedup vs baseline: 1.0074x; 1.0074x over previous
#include <cuda_runtime.h>
#include <cstdint>

// ---------------- problem constants ----------------
#define NBLK 148
#define NTHR 256
#define BB   256
#define NC   3072            // compact gate width (i, gg, o) -- f gate is dead
#define TT   256
#define VV   130
#define BH   (256*1024)
#define GS   (256*3072)

// ---------------- persistent device scratch ----------------
__device__ float d_cT   [16*256*512];
__device__ float d_cPrev[16*256*512];
__device__ float d_hid  [16*256*1024];
__device__ float d_A1   [3*16*256*3072];
__device__ float d_CU   [16*256*3072];
__device__ float d_C2   [3*16*256*3072];
__device__ float d_E    [3*130*3072];
__device__ float d_nb1  [3*3072];
__device__ float d_h1   [3*256*1024];
__device__ float d_h2   [3*256*1024];
__device__ float d_ctxs [3*256*1024];
__device__ float d_uold [3*256*1024];
__device__ float d_unew [2*256*1024];
__device__ float d_s    [3*256*3072];
__device__ float d_sn   [2*256*3072];
__device__ float d_g    [3*256*3072];

// ---------------- grid barrier (replay-safe, sense via generation) ----------
__device__ unsigned int g_arrive;
__device__ unsigned int g_gen;

__device__ __forceinline__ void gsync()
{
    __threadfence();
    __syncthreads();
    if (threadIdx.x == 0) {
        volatile unsigned int* vg = &g_gen;
        unsigned int g = *vg;
        if (atomicAdd(&g_arrive, 1u) == (unsigned)(gridDim.x - 1)) {
            g_arrive = 0;
            __threadfence();
            *vg = g + 1u;
        } else {
            while (*vg == g) __nanosleep(32);
        }
        __threadfence();
    }
    __syncthreads();
}

// ---------------- f32x2 helpers ----------------
__device__ __forceinline__ void fma2(unsigned long long &c, unsigned long long a,
                                     unsigned long long b) {
    asm("fma.rn.f32x2 %0, %1, %2, %0;" : "+l"(c) : "l"(a), "l"(b));
}
__device__ __forceinline__ unsigned long long dup2(float a) {
    unsigned long long r;
    asm("mov.b64 %0, {%1, %1};" : "=l"(r) : "f"(a));
    return r;
}
__device__ __forceinline__ void unpack2(unsigned long long v, float &lo, float &hi) {
    asm("mov.b64 {%0, %1}, %2;" : "=f"(lo), "=f"(hi) : "l"(v));
}

// ---------------- generic fused GEMM stage ----------------
struct GP {
    const float* A;  long long lda,  Az;
    const float* B;  long long ldb,  Bz;
    const float* A2; long long lda2, A2z;
    const float* B2; long long ldb2, B2z;
    int K, K2, M, N, zc, compact, epi;   // epi: 0 none, 1 tanh
    float* C; long long ldc, Cz;
    const float* add0; long long add0z;
    const float* add1;
    const float* add2;
    const float* bias; long long biasz; int biasCompact;
    const float* Eg;  long long Egz;
    const int*  tok;  long long tokz;  int tokstride;
};

__device__ __forceinline__ void run_mm(const float* A, long long lda, int M, int m0,
                                       const float* Bb, long long ldb, int N, int n0, int K,
                                       float (&As)[16][64], float (&Bs)[16][64],
                                       unsigned long long (&acc)[4][2],
                                       int tid, int tx, int ty)
{
    int r  = tid >> 2;
    int kq = (tid & 3) << 2;
    bool am = (m0 + r < M);
    bool bn = (n0 + r < N);
    const float* Arow = A  + (long long)(m0 + r) * lda + kq;
    const float* Brow = Bb + (long long)r * ldb + kq;
    for (int k0 = 0; k0 < K; k0 += 16) {
        float4 av = am ? *(const float4*)(Arow + k0) : make_float4(0.f,0.f,0.f,0.f);
        float4 bv = bn ? *(const float4*)(Brow + k0) : make_float4(0.f,0.f,0.f,0.f);
        As[kq+0][r]=av.x; As[kq+1][r]=av.y; As[kq+2][r]=av.z; As[kq+3][r]=av.w;
        Bs[kq+0][r]=bv.x; Bs[kq+1][r]=bv.y; Bs[kq+2][r]=bv.z; Bs[kq+3][r]=bv.w;
        __syncthreads();
#pragma unroll
        for (int kk = 0; kk < 16; kk++) {
            unsigned long long b0 = *(const unsigned long long*)&Bs[kk][tx*4];
            unsigned long long b1 = *(const unsigned long long*)&Bs[kk][tx*4+2];
#pragma unroll
            for (int mi = 0; mi < 4; mi++) {
                unsigned long long a2 = dup2(As[kk][ty*4+mi]);
                fma2(acc[mi][0], a2, b0);
                fma2(acc[mi][1], a2, b1);
            }
        }
        __syncthreads();
    }
}

__device__ void gemm_stage(const GP& g, float (&As)[16][64], float (&Bs)[16][64])
{
    int mT = (g.M + 63) >> 6;
    int nT = (g.N + 63) >> 6;
    int total = g.zc * mT * nT;
    int tid = threadIdx.x;
    int tx = tid & 15, ty = tid >> 4;

    for (int tile = blockIdx.x; tile < total; tile += gridDim.x) {
        int z  = tile / (mT * nT);
        int r  = tile - z * (mT * nT);
        int mi0 = r / nT;
        int m0 = mi0 << 6;
        int n0 = (r - mi0 * nT) << 6;
        int noff = (g.compact && n0 >= 1024) ? 1024 : 0;

        unsigned long long acc[4][2];
#pragma unroll
        for (int i = 0; i < 4; i++) { acc[i][0] = 0ull; acc[i][1] = 0ull; }

        {
            const float* A  = g.A + (long long)z * g.Az;
            const float* Bb = g.B + (long long)z * g.Bz + (long long)(n0 + noff) * g.ldb;
            run_mm(A, g.lda, g.M, m0, Bb, g.ldb, g.N, n0, g.K, As, Bs, acc, tid, tx, ty);
        }
        if (g.A2) {
            const float* A  = g.A2 + (long long)z * g.A2z;
            const float* Bb = g.B2 + (long long)z * g.B2z + (long long)(n0 + noff) * g.ldb2;
            run_mm(A, g.lda2, g.M, m0, Bb, g.ldb2, g.N, n0, g.K2, As, Bs, acc, tid, tx, ty);
        }

        float* C = g.C + (long long)z * g.Cz;
#pragma unroll
        for (int mi = 0; mi < 4; mi++) {
            int m = m0 + ty * 4 + mi;
            if (m >= g.M) continue;
            float cv[4];
            unpack2(acc[mi][0], cv[0], cv[1]);
            unpack2(acc[mi][1], cv[2], cv[3]);
            long long token = 0;
            if (g.Eg) token = g.tok[(long long)z * g.tokz + (long long)m * g.tokstride];
#pragma unroll
            for (int nj = 0; nj < 4; nj++) {
                int n = n0 + tx * 4 + nj;
                if (n >= g.N) continue;
                float v = cv[nj];
                if (g.add0) v += g.add0[(long long)z * g.add0z + (long long)m * g.N + n];
                if (g.add1) v += g.add1[(long long)m * g.N + n];
                if (g.add2) v += g.add2[(long long)m * g.N + n];
                if (g.bias) v += g.bias[(long long)z * g.biasz + (g.biasCompact ? (n + noff) : n)];
                if (g.Eg)   v += g.Eg[(long long)z * g.Egz + token * g.N + n];
                if (g.epi == 1) v = tanhf(v);
                C[(long long)m * g.ldc + n] = v;
            }
        }
    }
}

// gate: h = sigmoid(o) * tanh(sigmoid(i) * tanh(gg)); compact layout [i|gg|o]
__device__ void gate_stage(const float* gsrc, long long gz, int zc,
                           float* dst0, long long d0z, float* dst1, long long d1z)
{
    int total = zc << 18;
    for (int idx = blockIdx.x * NTHR + threadIdx.x; idx < total; idx += gridDim.x * NTHR) {
        int z   = idx >> 18;
        int rem = idx & ((1 << 18) - 1);
        int m = rem >> 10, j = rem & 1023;
        const float* gp = gsrc + (long long)z * gz + (long long)m * NC;
        float gi = gp[j], gg = gp[1024 + j], go = gp[2048 + j];
        float si = 1.f / (1.f + expf(-gi));
        float so = 1.f / (1.f + expf(-go));
        float v  = so * tanhf(si * tanhf(gg));
        long long o = (long long)z * d0z + (long long)m * 1024 + j;
        dst0[o] = v;
        if (dst1) dst1[(long long)z * d1z + (long long)m * 1024 + j] = v;
    }
}

__device__ void reset_stage(const float* hid)
{
    for (int idx = blockIdx.x * NTHR + threadIdx.x; idx < (1 << 18);
         idx += gridDim.x * NTHR) {
        float v = hid[idx];
        d_h1[idx] = v; d_h1[BH + idx] = v; d_h1[2 * BH + idx] = v;
        d_h2[idx] = v; d_h2[BH + idx] = v; d_h2[2 * BH + idx] = v;
        d_ctxs[2 * BH + idx] = v;
    }
}

__device__ void prep_stage(const float* c)
{
    for (int idx = blockIdx.x * NTHR + threadIdx.x; idx < (16 * 256 * 512);
         idx += gridDim.x * NTHR) {
        int ptr = idx >> 17;
        int rem = idx & 131071;
        int b = rem >> 9, k = rem & 511;
        d_cT[idx] = c[((b << 4) + ptr) * 512 + k];
        int pm = ptr > 0 ? ptr - 1 : 0;
        d_cPrev[idx] = c[((b << 4) + pm) * 512 + k];
    }
}

__device__ void nb1_stage(const float* emb, const float* W1ih, const float* b1)
{
    for (int idx = blockIdx.x * NTHR + threadIdx.x; idx < 3 * 3072;
         idx += gridDim.x * NTHR) {
        int i = idx / 3072, n = idx - (idx / 3072) * 3072;
        int nfull = n + (n >= 1024 ? 1024 : 0);
        const float* e = emb + (long long)i * 130 * 512;            // v = 0 row
        const float* w = W1ih + ((long long)i * 4096 + nfull) * 1024;
        float s = b1[i * 4096 + nfull];
        for (int k = 0; k < 512; k++) s += e[k] * w[k];
        d_nb1[idx] = s;
    }
}

// ---------------- the single persistent kernel ----------------
__global__ void __launch_bounds__(NTHR, 1)
mega_kernel(const float* c, const float* W1ih, const float* W1hh, const float* b1,
            const float* cWih, const float* cWhh, const float* cb,
            const float* W2ih, const float* W2hh, const float* b2,
            const float* outW, const float* outb,
            const float* hidW, const float* hidb,
            const float* emb, const int* tgt, float* out)
{
    __shared__ __align__(16) float As[16][64];
    __shared__ __align__(16) float Bs[16][64];

    // ---- phase 0: transpose + notes0 hoist ----
    prep_stage(c);
    nb1_stage(emb, W1ih, b1);
    gsync();

    // ---- phase 1: all per-bar hoisted GEMMs ----
    { // hidden[ptr] = tanh(cPrev @ hidW^T + hidb)
        GP g = {};
        g.A = d_cPrev; g.lda = 512; g.B = hidW; g.ldb = 512;
        g.K = 512; g.M = 4096; g.N = 1024; g.zc = 1; g.epi = 1;
        g.C = d_hid; g.ldc = 1024;
        g.bias = hidb;
        gemm_stage(g, As, Bs);
    }
    { // A1[i][ptr] = nb1[i] + cT @ W1ih[i][:,512:]^T
        GP g = {};
        g.A = d_cT; g.lda = 512;
        g.B = W1ih + 512; g.ldb = 1024; g.Bz = (long long)4096 * 1024;
        g.K = 512; g.M = 4096; g.N = NC; g.zc = 3; g.compact = 1;
        g.C = d_A1; g.ldc = NC; g.Cz = (long long)16 * GS;
        g.bias = d_nb1; g.biasz = NC;
        gemm_stage(g, As, Bs);
    }
    { // CU[ptr] = cT @ W1ih[1][:,512:]^T + b1[1]
        GP g = {};
        g.A = d_cT; g.lda = 512;
        g.B = W1ih + (long long)4096 * 1024 + 512; g.ldb = 1024;
        g.K = 512; g.M = 4096; g.N = NC; g.zc = 1; g.compact = 1;
        g.C = d_CU; g.ldc = NC;
        g.bias = b1 + 4096; g.biasCompact = 1;
        gemm_stage(g, As, Bs);
    }
    { // C2[i][ptr] = cT @ W2ih[i][:,1024:]^T + b2[i]
        GP g = {};
        g.A = d_cT; g.lda = 512;
        g.B = W2ih + 1024; g.ldb = 1536; g.Bz = (long long)4096 * 1536;
        g.K = 512; g.M = 4096; g.N = NC; g.zc = 3; g.compact = 1;
        g.C = d_C2; g.ldc = NC; g.Cz = (long long)16 * GS;
        g.bias = b2; g.biasz = 4096; g.biasCompact = 1;
        gemm_stage(g, As, Bs);
    }
    { // E = emb @ W1ih[1][:, :512]^T
        GP g = {};
        g.A = emb; g.lda = 512;
        g.B = W1ih + (long long)4096 * 1024; g.ldb = 1024;
        g.K = 512; g.M = 390; g.N = NC; g.zc = 1; g.compact = 1;
        g.C = d_E; g.ldc = NC;
        gemm_stage(g, As, Bs);
    }
    gsync();

    // ---- time loop ----
    for (int t = 0; t < TT; t++) {
        int ptr = t >> 4;
        if ((t & 15) == 0) {
            reset_stage(d_hid + (long long)ptr * BH);
            gsync();
        }

        { // g = A1[.,ptr] + h1 @ W1hh^T
            GP g = {};
            g.A = d_h1; g.lda = 1024; g.Az = BH;
            g.B = W1hh; g.ldb = 1024; g.Bz = (long long)4096 * 1024;
            g.K = 1024; g.M = BB; g.N = NC; g.zc = 3; g.compact = 1;
            g.C = d_g; g.ldc = NC; g.Cz = GS;
            g.add0 = d_A1 + (long long)ptr * GS; g.add0z = (long long)16 * GS;
            gemm_stage(g, As, Bs);
        }
        gsync();
        gate_stage(d_g, GS, 3, d_h1, BH, d_uold, BH);
        gsync();

        { // s[i] = uold[i] @ ctxWih slice^T
            GP g = {};
            g.A = d_uold; g.lda = 1024; g.Az = BH;
            g.B = cWih; g.ldb = NC; g.Bz = 1024;
            g.K = 1024; g.M = BB; g.N = NC; g.zc = 3; g.compact = 1;
            g.C = d_s; g.ldc = NC; g.Cz = GS;
            gemm_stage(g, As, Bs);
        }
        { // gu[i] = E[i][tok] + CU[ptr] + uold[i] @ W1hh[1]^T   (i = 0,1)
            GP g = {};
            g.A = d_uold; g.lda = 1024; g.Az = BH;
            g.B = W1hh + (long long)4096 * 1024; g.ldb = 1024;
            g.K = 1024; g.M = BB; g.N = NC; g.zc = 2; g.compact = 1;
            g.C = d_g; g.ldc = NC; g.Cz = GS;
            g.add0 = d_CU + (long long)ptr * GS; g.add0z = 0;
            g.Eg = d_E; g.Egz = (long long)130 * NC;
            g.tok = tgt + t; g.tokz = 65536; g.tokstride = 256;
            gemm_stage(g, As, Bs);
        }
        gsync();
        gate_stage(d_g, GS, 2, d_unew, BH, (float*)0, 0);
        gsync();

        { // sn[i] = unew[i] @ ctxWih slice^T  (i = 0,1)
            GP g = {};
            g.A = d_unew; g.lda = 1024; g.Az = BH;
            g.B = cWih; g.ldb = NC; g.Bz = 1024;
            g.K = 1024; g.M = BB; g.N = NC; g.zc = 2; g.compact = 1;
            g.C = d_sn; g.ldc = NC; g.Cz = GS;
            gemm_stage(g, As, Bs);
        }
        { // ctx update 0 (can share phase with sn)
            GP g = {};
            g.A = d_ctxs + 2 * (long long)BH; g.lda = 1024;
            g.B = cWhh; g.ldb = 1024;
            g.K = 1024; g.M = BB; g.N = NC; g.zc = 1; g.compact = 1;
            g.C = d_g; g.ldc = NC;
            g.add0 = d_s; g.add0z = 0;
            g.add1 = d_s + GS; g.add2 = d_s + 2 * (long long)GS;
            g.bias = cb; g.biasCompact = 1;
            gemm_stage(g, As, Bs);
        }
        gsync();
        gate_stage(d_g, 0, 1, d_ctxs, 0, (float*)0, 0);
        gsync();

        { // ctx update 1
            GP g = {};
            g.A = d_ctxs; g.lda = 1024;
            g.B = cWhh; g.ldb = 1024;
            g.K = 1024; g.M = BB; g.N = NC; g.zc = 1; g.compact = 1;
            g.C = d_g; g.ldc = NC;
            g.add0 = d_sn; g.add0z = 0;
            g.add1 = d_s + GS; g.add2 = d_s + 2 * (long long)GS;
            g.bias = cb; g.biasCompact = 1;
            gemm_stage(g, As, Bs);
        }
        gsync();
        gate_stage(d_g, 0, 1, d_ctxs + BH, 0, (float*)0, 0);
        gsync();

        { // ctx update 2
            GP g = {};
            g.A = d_ctxs + (long long)BH; g.lda = 1024;
            g.B = cWhh; g.ldb = 1024;
            g.K = 1024; g.M = BB; g.N = NC; g.zc = 1; g.compact = 1;
            g.C = d_g; g.ldc = NC;
            g.add0 = d_sn; g.add0z = 0;
            g.add1 = d_sn + GS; g.add2 = d_s + 2 * (long long)GS;
            g.bias = cb; g.biasCompact = 1;
            gemm_stage(g, As, Bs);
        }
        gsync();
        gate_stage(d_g, 0, 1, d_ctxs + 2 * (long long)BH, 0, (float*)0, 0);
        gsync();

        { // g2[i] = ctxs[i] @ W2ih[i][:, :1024]^T + h2[i] @ W2hh[i]^T + C2[i][ptr]
            GP g = {};
            g.A = d_ctxs; g.lda = 1024; g.Az = BH;
            g.B = W2ih; g.ldb = 1536; g.Bz = (long long)4096 * 1536;
            g.K = 1024;
            g.A2 = d_h2; g.lda2 = 1024; g.A2z = BH;
            g.B2 = W2hh; g.ldb2 = 1024; g.B2z = (long long)4096 * 1024;
            g.K2 = 1024;
            g.M = BB; g.N = NC; g.zc = 3; g.compact = 1;
            g.C = d_g; g.ldc = NC; g.Cz = GS;
            g.add0 = d_C2 + (long long)ptr * GS; g.add0z = (long long)16 * GS;
            gemm_stage(g, As, Bs);
        }
        gsync();
        gate_stage(d_g, GS, 3, d_h2, BH, (float*)0, 0);
        gsync();

        { // out[i][:,t,:] = (uold[i] + h2[i]) @ outW[i]^T + outb[i]
            GP g = {};
            g.A = d_uold; g.lda = 1024; g.Az = BH;
            g.B = outW; g.ldb = 1024; g.Bz = (long long)130 * 1024;
            g.K = 1024;
            g.A2 = d_h2; g.lda2 = 1024; g.A2z = BH;
            g.B2 = outW; g.ldb2 = 1024; g.B2z = (long long)130 * 1024;
            g.K2 = 1024;
            g.M = BB; g.N = VV; g.zc = 3;
            g.C = out + (long long)t * VV; g.ldc = (long long)TT * VV;
            g.Cz = (long long)BB * TT * VV;
            g.bias = outb; g.biasz = VV;
            gemm_stage(g, As, Bs);
        }
        gsync();   // protects uold/h2 (read by OUT) from next step's writers
    }
}

// ---------------- host ----------------
extern "C" void kernel_launch(void* const* d_in, const int* in_sizes, int n_in,
                              void* d_out, int out_size)
{
    (void)in_sizes; (void)n_in; (void)out_size;
    mega_kernel<<<NBLK, NTHR>>>(
        (const float*)d_in[0],  (const float*)d_in[1],  (const float*)d_in[2],
        (const float*)d_in[3],  (const float*)d_in[4],  (const float*)d_in[5],
        (const float*)d_in[6],  (const float*)d_in[7],  (const float*)d_in[8],
        (const float*)d_in[9],  (const float*)d_in[10], (const float*)d_in[11],
        (const float*)d_in[12], (const float*)d_in[13], (const float*)d_in[14],
        (const int*)d_in[15],   (float*)d_out);
}